// round 5
// baseline (speedup 1.0000x reference)
#include <cuda_runtime.h>
#include <cstdint>

// Problem constants
#define B_ROWS  4096
#define D_MODEL 768
#define DICT    24576
#define TOPK    64
#define DELTA   1e-4f   // boundary ambiguity window (>> 6*sigma of fp32 GEMM error)

// ---------------------------------------------------------------------------
// Scratch (static __device__ globals: allocation-free per harness rules)
// ---------------------------------------------------------------------------
__device__ float g_pre[(size_t)B_ROWS * DICT];      // 402.7 MB pre-activations
__device__ float g_wdecT[(size_t)DICT * D_MODEL];   // 75.5 MB transposed decoder
__device__ int   g_cidx[B_ROWS * TOPK];             // compact top-k indices
__device__ float g_cval[B_ROWS * TOPK];             // compact top-k values (post-relu)

// ---------------------------------------------------------------------------
// K1: transpose W_dec [D_MODEL, DICT] -> W_decT [DICT, D_MODEL]
// ---------------------------------------------------------------------------
__global__ void transpose_kernel(const float* __restrict__ W)
{
    __shared__ float tile[32][33];
    const int tx = threadIdx.x;         // 0..31
    const int ty = threadIdx.y;         // 0..7
    const int x = blockIdx.x * 32 + tx; // along DICT (f)
    const int y = blockIdx.y * 32 + ty; // along D_MODEL (d)

    #pragma unroll
    for (int r = 0; r < 32; r += 8)
        tile[ty + r][tx] = W[(size_t)(y + r) * DICT + x];
    __syncthreads();

    const int xo = blockIdx.y * 32 + tx; // d
    const int yo = blockIdx.x * 32 + ty; // f
    #pragma unroll
    for (int r = 0; r < 32; r += 8)
        g_wdecT[(size_t)(yo + r) * D_MODEL + xo] = tile[tx][ty + r];
}

// ---------------------------------------------------------------------------
// K2: fp32 SGEMM  pre[b,f] = sum_d x[b,d]*W_enc[f,d] + b_enc[f]
// 128x128 block tile, BK=16, 8x8 per thread, double-buffered smem.
// ---------------------------------------------------------------------------
__global__ __launch_bounds__(256, 2) void sgemm_enc_kernel(
    const float* __restrict__ x,
    const float* __restrict__ Wenc,
    const float* __restrict__ bias)
{
    __shared__ float As[2][16][128];
    __shared__ float Bs[2][16][128];

    const int tid = threadIdx.x;
    const int tx  = tid & 15;           // 0..15 (n)
    const int ty  = tid >> 4;           // 0..15 (m)
    const int bF  = blockIdx.x * 128;   // feature tile
    const int bB  = blockIdx.y * 128;   // batch tile

    const int lr = tid >> 2;            // 0..63 (tile row for loads)
    const int lc = (tid & 3) << 2;      // 0,4,8,12 (k offset, float4)

    const float* Ap0 = x    + (size_t)(bB + lr) * D_MODEL + lc;
    const float* Ap1 = Ap0  + (size_t)64 * D_MODEL;
    const float* Bp0 = Wenc + (size_t)(bF + lr) * D_MODEL + lc;
    const float* Bp1 = Bp0  + (size_t)64 * D_MODEL;

    float4 pa0 = *(const float4*)Ap0;
    float4 pa1 = *(const float4*)Ap1;
    float4 pb0 = *(const float4*)Bp0;
    float4 pb1 = *(const float4*)Bp1;

    float acc[8][8];
    #pragma unroll
    for (int i = 0; i < 8; ++i)
        #pragma unroll
        for (int j = 0; j < 8; ++j)
            acc[i][j] = 0.0f;

    int buf = 0;
    const int NKT = D_MODEL / 16;       // 48
    for (int kt = 0; kt < NKT; ++kt) {
        As[buf][lc + 0][lr]      = pa0.x;
        As[buf][lc + 1][lr]      = pa0.y;
        As[buf][lc + 2][lr]      = pa0.z;
        As[buf][lc + 3][lr]      = pa0.w;
        As[buf][lc + 0][lr + 64] = pa1.x;
        As[buf][lc + 1][lr + 64] = pa1.y;
        As[buf][lc + 2][lr + 64] = pa1.z;
        As[buf][lc + 3][lr + 64] = pa1.w;
        Bs[buf][lc + 0][lr]      = pb0.x;
        Bs[buf][lc + 1][lr]      = pb0.y;
        Bs[buf][lc + 2][lr]      = pb0.z;
        Bs[buf][lc + 3][lr]      = pb0.w;
        Bs[buf][lc + 0][lr + 64] = pb1.x;
        Bs[buf][lc + 1][lr + 64] = pb1.y;
        Bs[buf][lc + 2][lr + 64] = pb1.z;
        Bs[buf][lc + 3][lr + 64] = pb1.w;
        __syncthreads();

        if (kt + 1 < NKT) {
            const int o = (kt + 1) * 16;
            pa0 = *(const float4*)(Ap0 + o);
            pa1 = *(const float4*)(Ap1 + o);
            pb0 = *(const float4*)(Bp0 + o);
            pb1 = *(const float4*)(Bp1 + o);
        }

        #pragma unroll
        for (int k = 0; k < 16; ++k) {
            float a[8], b[8];
            *(float4*)&a[0] = *(const float4*)&As[buf][k][ty * 8];
            *(float4*)&a[4] = *(const float4*)&As[buf][k][ty * 8 + 4];
            *(float4*)&b[0] = *(const float4*)&Bs[buf][k][tx * 8];
            *(float4*)&b[4] = *(const float4*)&Bs[buf][k][tx * 8 + 4];
            #pragma unroll
            for (int i = 0; i < 8; ++i)
                #pragma unroll
                for (int j = 0; j < 8; ++j)
                    acc[i][j] += a[i] * b[j];
        }
        buf ^= 1;
    }

    float bb[8];
    *(float4*)&bb[0] = *(const float4*)(bias + bF + tx * 8);
    *(float4*)&bb[4] = *(const float4*)(bias + bF + tx * 8 + 4);
    #pragma unroll
    for (int i = 0; i < 8; ++i) {
        float* orow = g_pre + (size_t)(bB + ty * 8 + i) * DICT + bF + tx * 8;
        float4 v0, v1;
        v0.x = acc[i][0] + bb[0]; v0.y = acc[i][1] + bb[1];
        v0.z = acc[i][2] + bb[2]; v0.w = acc[i][3] + bb[3];
        v1.x = acc[i][4] + bb[4]; v1.y = acc[i][5] + bb[5];
        v1.z = acc[i][6] + bb[6]; v1.w = acc[i][7] + bb[7];
        *(float4*)orow       = v0;
        *(float4*)(orow + 4) = v1;
    }
}

// ---------------------------------------------------------------------------
// K3: exact per-row top-64.
//  a) 4-pass MSB radix select on monotone keys -> fp32 64th value Tv
//  b) classify: sure-in (v > Tv+DELTA), candidate (|v-Tv| <= DELTA)
//  c) if candidates exceed open slots: re-score candidates with exact fp64
//     dot products (deterministic tree reduction), pick by (score, -idx).
// This makes the selected SET independent of fp32 GEMM accumulation order.
// ---------------------------------------------------------------------------
#define TK_THREADS 256
#define TK_SMEM_BYTES ((DICT + 8 * 256) * 4)   // keys + 8KB aux

__device__ __forceinline__ unsigned f2k(unsigned u) {
    return (u & 0x80000000u) ? ~u : (u | 0x80000000u);
}
__device__ __forceinline__ float k2f(unsigned k) {
    unsigned u = (k & 0x80000000u) ? (k ^ 0x80000000u) : ~k;
    return __uint_as_float(u);
}

__global__ __launch_bounds__(TK_THREADS) void topk_kernel(
    const float* __restrict__ x,
    const float* __restrict__ Wenc,
    float* __restrict__ acts)
{
    extern __shared__ unsigned sm[];
    unsigned* keys = sm;            // [DICT]
    unsigned* aux  = sm + DICT;     // 8KB: radix hists, later x-row + reduce

    __shared__ unsigned s_need, s_sel, s_ns, s_nc;
    __shared__ int      cand_idx[64];
    __shared__ float    cand_val[64];
    __shared__ double   cand_score[64];
    __shared__ unsigned char chosen[64];

    const int tid = threadIdx.x;
    const int wid = tid >> 5;
    const int b   = blockIdx.x;
    const float* row  = g_pre + (size_t)b * DICT;
    float*       arow = acts  + (size_t)b * DICT;

    // monotone float->uint keys, vectorized
    {
        const uint4* row4 = (const uint4*)row;
        for (int i = tid; i < DICT / 4; i += TK_THREADS) {
            uint4 u = row4[i];
            uint4 kk;
            kk.x = f2k(u.x); kk.y = f2k(u.y); kk.z = f2k(u.z); kk.w = f2k(u.w);
            *(uint4*)&keys[i * 4] = kk;
        }
    }
    if (tid == 0) { s_need = TOPK; s_ns = 0; s_nc = 0; }
    __syncthreads();

    // ---- radix select: find key of the 64th largest ----
    unsigned prefix = 0;
    for (int pass = 0; pass < 4; ++pass) {
        const int shift = 24 - 8 * pass;
        for (int i = tid; i < 8 * 256; i += TK_THREADS) aux[i] = 0;
        __syncthreads();
        const unsigned hi_mask = (pass == 0) ? 0u : (0xFFFFFFFFu << (shift + 8));
        for (int i = tid; i < DICT; i += TK_THREADS) {
            const unsigned key = keys[i];
            if ((key & hi_mask) == prefix)
                atomicAdd(&aux[(wid << 8) + ((key >> shift) & 255u)], 1u);
        }
        __syncthreads();
        unsigned cnt = 0;
        #pragma unroll
        for (int w = 0; w < 8; ++w) cnt += aux[(w << 8) + tid];
        aux[tid] = cnt;
        __syncthreads();
        if (tid == 0) {
            unsigned need = s_need, accum = 0;
            int sel = 0;
            for (int bkt = 255; bkt >= 0; --bkt) {
                const unsigned c = aux[bkt];
                if (accum + c >= need) { sel = bkt; break; }
                accum += c;
            }
            s_need = need - accum;
            s_sel  = (unsigned)sel;
        }
        __syncthreads();
        prefix |= (s_sel << shift);
    }
    const float Tv = k2f(prefix);    // fp32 value of the 64th largest

    // ---- zero the output acts row ----
    {
        float4 z = make_float4(0.f, 0.f, 0.f, 0.f);
        float4* a4 = (float4*)arow;
        for (int i = tid; i < DICT / 4; i += TK_THREADS) a4[i] = z;
    }
    __syncthreads();

    // ---- classify: sure-ins written directly, candidates buffered ----
    const float hi = Tv + DELTA;
    const float lo = Tv - DELTA;
    for (int i = tid; i < DICT; i += TK_THREADS) {
        const float v = k2f(keys[i]);
        if (v > hi) {
            const unsigned slot = atomicAdd(&s_ns, 1u);
            const float rv = fmaxf(v, 0.0f);
            arow[i] = rv;
            g_cidx[b * TOPK + slot] = i;
            g_cval[b * TOPK + slot] = rv;
        } else if (v >= lo) {
            const unsigned c = atomicAdd(&s_nc, 1u);
            if (c < 64u) { cand_idx[c] = i; cand_val[c] = v; }
        }
    }
    __syncthreads();

    const int ns   = (int)s_ns;
    const int need = TOPK - ns;               // >= 1 by construction
    const int nc   = (int)min(s_nc, 64u);

    if (nc <= need) {
        // no ambiguity: take all candidates
        for (int j = tid; j < nc; j += TK_THREADS) {
            const int   i  = cand_idx[j];
            const float rv = fmaxf(cand_val[j], 0.0f);
            arow[i] = rv;
            g_cidx[b * TOPK + ns + j] = i;
            g_cval[b * TOPK + ns + j] = rv;
        }
        return;
    }

    // ---- ambiguous boundary: exact fp64 re-scoring of candidates ----
    float*  xs  = (float*)aux;                 // 768 floats (3KB)
    double* red = (double*)(aux + 1024);       // 256 doubles (2KB) at +4KB
    for (int d = tid; d < D_MODEL; d += TK_THREADS) xs[d] = x[(size_t)b * D_MODEL + d];
    __syncthreads();

    for (int c = 0; c < nc; ++c) {
        const float* wr = Wenc + (size_t)cand_idx[c] * D_MODEL;
        double p = 0.0;
        for (int d = tid; d < D_MODEL; d += TK_THREADS)
            p += (double)xs[d] * (double)wr[d];
        red[tid] = p;
        __syncthreads();
        for (int s = TK_THREADS / 2; s > 0; s >>= 1) {
            if (tid < s) red[tid] += red[tid + s];
            __syncthreads();
        }
        if (tid == 0) cand_score[c] = red[0];
        __syncthreads();
    }

    if (tid == 0) {
        for (int c = 0; c < nc; ++c) chosen[c] = 0;
        int slot = ns;
        for (int n = 0; n < need; ++n) {
            int best = -1;
            for (int c = 0; c < nc; ++c) {
                if (chosen[c]) continue;
                if (best < 0 ||
                    cand_score[c] > cand_score[best] ||
                    (cand_score[c] == cand_score[best] && cand_idx[c] < cand_idx[best]))
                    best = c;
            }
            chosen[best] = 1;
            const int   i  = cand_idx[best];
            const float rv = fmaxf(cand_val[best], 0.0f);
            arow[i] = rv;
            g_cidx[b * TOPK + slot] = i;
            g_cval[b * TOPK + slot] = rv;
            ++slot;
        }
    }
}

// ---------------------------------------------------------------------------
// K4: sparse decoder  recon[b,:] = sum_{j<64} val_j * W_decT[idx_j, :]
// ---------------------------------------------------------------------------
__global__ __launch_bounds__(256) void dec_kernel(float* __restrict__ recon)
{
    __shared__ int   sidx[TOPK];
    __shared__ float sval[TOPK];
    const int tid = threadIdx.x;
    const int b   = blockIdx.x;

    if (tid < TOPK) {
        sidx[tid] = g_cidx[b * TOPK + tid];
        sval[tid] = g_cval[b * TOPK + tid];
    }
    __syncthreads();

    float acc0 = 0.0f, acc1 = 0.0f, acc2 = 0.0f;
    const int d0 = tid, d1 = tid + 256, d2 = tid + 512;
    #pragma unroll 4
    for (int j = 0; j < TOPK; ++j) {
        const float* wr = g_wdecT + (size_t)sidx[j] * D_MODEL;
        const float  v  = sval[j];
        acc0 += v * wr[d0];
        acc1 += v * wr[d1];
        acc2 += v * wr[d2];
    }
    float* orow = recon + (size_t)b * D_MODEL;
    orow[d0] = acc0;
    orow[d1] = acc1;
    orow[d2] = acc2;
}

// ---------------------------------------------------------------------------
// Launch: out = [recon (B*D_MODEL) | acts (B*DICT)] fp32
// ---------------------------------------------------------------------------
extern "C" void kernel_launch(void* const* d_in, const int* in_sizes, int n_in,
                              void* d_out, int out_size)
{
    const float* x     = (const float*)d_in[0];
    const float* W_enc = (const float*)d_in[1];
    const float* b_enc = (const float*)d_in[2];
    const float* W_dec = (const float*)d_in[3];
    (void)in_sizes; (void)n_in; (void)out_size;   // k hardcoded to 64

    float* recon = (float*)d_out;
    float* acts  = (float*)d_out + (size_t)B_ROWS * D_MODEL;

    cudaFuncSetAttribute(topk_kernel,
                         cudaFuncAttributeMaxDynamicSharedMemorySize,
                         TK_SMEM_BYTES);

    transpose_kernel<<<dim3(DICT / 32, D_MODEL / 32), dim3(32, 8)>>>(W_dec);
    sgemm_enc_kernel<<<dim3(DICT / 128, B_ROWS / 128), 256>>>(x, W_enc, b_enc);
    topk_kernel<<<B_ROWS, TK_THREADS, TK_SMEM_BYTES>>>(x, W_enc, acts);
    dec_kernel<<<B_ROWS, 256>>>(recon);
}

// round 6
// speedup vs baseline: 2.4931x; 2.4931x over previous
#include <cuda_runtime.h>
#include <cstdint>

// Problem constants
#define B_ROWS  4096
#define D_MODEL 768
#define DICT    24576
#define TOPK    64
#define DELTA   6e-3f   // candidate window: ~9 sigma of tf32 coarse-score noise

// ---------------------------------------------------------------------------
// Scratch (static __device__ globals: allocation-free per harness rules)
// ---------------------------------------------------------------------------
__device__ float g_pre[(size_t)B_ROWS * DICT];      // coarse pre-activations
__device__ float g_wdecT[(size_t)DICT * D_MODEL];   // transposed decoder
__device__ int   g_cidx[B_ROWS * TOPK];             // selected indices
__device__ float g_cval[B_ROWS * TOPK];             // exact values (post-relu)

// ---------------------------------------------------------------------------
// PTX helpers
// ---------------------------------------------------------------------------
#define CPA16(dst, src) \
    asm volatile("cp.async.cg.shared.global [%0], [%1], 16;" :: "r"(dst), "l"(src))
#define CPA_COMMIT() asm volatile("cp.async.commit_group;" ::: "memory")
#define CPA_WAIT0()  asm volatile("cp.async.wait_group 0;" ::: "memory")

#define LDMX4(r, addr) \
    asm volatile("ldmatrix.sync.aligned.m8n8.x4.shared.b16 {%0,%1,%2,%3}, [%4];" \
        : "=r"((r)[0]), "=r"((r)[1]), "=r"((r)[2]), "=r"((r)[3]) : "r"(addr))

#define MMA_TF32(acc, a, b0, b1) \
    asm volatile("mma.sync.aligned.m16n8k8.row.col.f32.tf32.tf32.f32 " \
        "{%0,%1,%2,%3}, {%4,%5,%6,%7}, {%8,%9}, {%0,%1,%2,%3};" \
        : "+f"((acc)[0]), "+f"((acc)[1]), "+f"((acc)[2]), "+f"((acc)[3]) \
        : "r"((a)[0]), "r"((a)[1]), "r"((a)[2]), "r"((a)[3]), "r"(b0), "r"(b1))

// ---------------------------------------------------------------------------
// K1: transpose W_dec [D_MODEL, DICT] -> W_decT [DICT, D_MODEL]
// ---------------------------------------------------------------------------
__global__ void transpose_kernel(const float* __restrict__ W)
{
    __shared__ float tile[32][33];
    const int tx = threadIdx.x, ty = threadIdx.y;
    const int x = blockIdx.x * 32 + tx;
    const int y = blockIdx.y * 32 + ty;

    #pragma unroll
    for (int r = 0; r < 32; r += 8)
        tile[ty + r][tx] = W[(size_t)(y + r) * DICT + x];
    __syncthreads();

    const int xo = blockIdx.y * 32 + tx;
    const int yo = blockIdx.x * 32 + ty;
    #pragma unroll
    for (int r = 0; r < 32; r += 8)
        g_wdecT[(size_t)(yo + r) * D_MODEL + xo] = tile[tx][ty + r];
}

// ---------------------------------------------------------------------------
// K2: tf32 tensor-core GEMM  pre[b,f] = sum_d x[b,d]*W_enc[f,d] + b_enc[f]
// CTA tile 128x128, BK=32, 8 warps (4M x 2N), m16n8k8 tf32 mma.
// smem: A[2][128][32] + B[2][128][32] fp32, SW128 swizzle, cp.async double buf.
// ---------------------------------------------------------------------------
#define GEMM_SMEM_BYTES 65536

__global__ __launch_bounds__(256, 2) void tf32_gemm_kernel(
    const float* __restrict__ x,
    const float* __restrict__ Wenc,
    const float* __restrict__ bias)
{
    extern __shared__ float smem[];
    const int tid  = threadIdx.x;
    const int lane = tid & 31;
    const int wid  = tid >> 5;
    const int wm   = wid & 3;            // M warp: 32*wm
    const int wn   = wid >> 2;           // N warp: 64*wn
    const int bF   = blockIdx.x * 128;
    const int bB   = blockIdx.y * 128;

    const uint32_t sbase = (uint32_t)__cvta_generic_to_shared(smem);
    const uint32_t sA = sbase;           // stage stride 16384 B
    const uint32_t sB = sbase + 32768;

    // ---- loader setup: each thread moves 4x16B for A and B per stage ----
    const int lrow = tid >> 3;           // 0..31
    const int lc16 = tid & 7;            // 0..7
    const float* gA = x    + (size_t)(bB + lrow) * D_MODEL + lc16 * 4;
    const float* gB = Wenc + (size_t)(bF + lrow) * D_MODEL + lc16 * 4;
    uint32_t dOff[4];
    #pragma unroll
    for (int j = 0; j < 4; ++j) {
        const int r = lrow + 32 * j;
        dOff[j] = (uint32_t)(r * 128 + ((lc16 * 16) ^ ((r & 7) << 4)));
    }

    // ---- ldmatrix address setup ----
    // lane l supplies address for row (l&7) of matrix (l>>3)
    const int mat  = lane >> 3;
    const int mrow = lane & 7;
    // A: matrices = {rows0-7 kh0, rows8-15 kh0, rows0-7 kh1, rows8-15 kh1}
    const int aRow0   = wm * 32 + (mat & 1) * 8 + mrow;   // tm=0; tm=1 adds 16
    const uint32_t aX = (uint32_t)((aRow0 & 7) << 4);     // same for tm=1
    const int aKh     = mat >> 1;
    // B: matrices = {n0-7 kh0, n0-7 kh1, n8-15 kh0, n8-15 kh1} per pair p
    const int bRow0   = wn * 64 + (mat >> 1) * 8 + mrow;  // p=0; p adds 16
    const uint32_t bX = (uint32_t)((bRow0 & 7) << 4);
    const int bKh     = mat & 1;

    float acc[2][8][4];
    #pragma unroll
    for (int tm = 0; tm < 2; ++tm)
        #pragma unroll
        for (int tn = 0; tn < 8; ++tn)
            #pragma unroll
            for (int q = 0; q < 4; ++q) acc[tm][tn][q] = 0.0f;

    // ---- prologue: stage 0 ----
    #pragma unroll
    for (int j = 0; j < 4; ++j) {
        CPA16(sA + dOff[j], gA + (size_t)(32 * j) * D_MODEL);
        CPA16(sB + dOff[j], gB + (size_t)(32 * j) * D_MODEL);
    }
    CPA_COMMIT();
    CPA_WAIT0();
    __syncthreads();

    const int NKT = D_MODEL / 32;        // 24
    for (int kt = 0; kt < NKT; ++kt) {
        const uint32_t cur = (kt & 1) * 16384u;
        const uint32_t nxt = 16384u - cur;
        if (kt + 1 < NKT) {
            const int ko = (kt + 1) * 32;
            #pragma unroll
            for (int j = 0; j < 4; ++j) {
                CPA16(sA + nxt + dOff[j], gA + (size_t)(32 * j) * D_MODEL + ko);
                CPA16(sB + nxt + dOff[j], gB + (size_t)(32 * j) * D_MODEL + ko);
            }
            CPA_COMMIT();
        }

        #pragma unroll
        for (int ks = 0; ks < 4; ++ks) {
            uint32_t a0[4], a1[4], bf[4][4];
            const uint32_t aK = ((uint32_t)(ks << 5) | (uint32_t)(aKh << 4)) ^ aX;
            const uint32_t bK = ((uint32_t)(ks << 5) | (uint32_t)(bKh << 4)) ^ bX;
            LDMX4(a0, sA + cur + (uint32_t)(aRow0 * 128) + aK);
            LDMX4(a1, sA + cur + (uint32_t)((aRow0 + 16) * 128) + aK);
            #pragma unroll
            for (int p = 0; p < 4; ++p)
                LDMX4(bf[p], sB + cur + (uint32_t)((bRow0 + p * 16) * 128) + bK);

            #pragma unroll
            for (int tn = 0; tn < 8; ++tn) {
                const int p  = tn >> 1;
                const int i0 = (tn & 1) * 2;
                MMA_TF32(acc[0][tn], a0, bf[p][i0], bf[p][i0 + 1]);
                MMA_TF32(acc[1][tn], a1, bf[p][i0], bf[p][i0 + 1]);
            }
        }

        if (kt + 1 < NKT) CPA_WAIT0();
        __syncthreads();
    }

    // ---- epilogue: add bias, store coarse scores ----
    const int g  = lane >> 2;
    const int tg = lane & 3;
    #pragma unroll
    for (int tn = 0; tn < 8; ++tn) {
        const int col = bF + wn * 64 + tn * 8 + tg * 2;
        const float2 bv = *(const float2*)(bias + col);
        #pragma unroll
        for (int tm = 0; tm < 2; ++tm) {
            const int r0 = bB + wm * 32 + tm * 16 + g;
            float2 v0, v1;
            v0.x = acc[tm][tn][0] + bv.x; v0.y = acc[tm][tn][1] + bv.y;
            v1.x = acc[tm][tn][2] + bv.x; v1.y = acc[tm][tn][3] + bv.y;
            *(float2*)&g_pre[(size_t)r0 * DICT + col]       = v0;
            *(float2*)&g_pre[(size_t)(r0 + 8) * DICT + col] = v1;
        }
    }
}

// ---------------------------------------------------------------------------
// K3: per-row top-64 selection on coarse scores.
//  a) 4-pass radix select -> coarse 64th value Tc
//  b) sure-in: v > Tc+DELTA (indices out directly); candidates |v-Tc|<=DELTA
//  c) ambiguity -> exact fp64 rescore of candidates, pick by (score,-idx)
//  Writes g_cidx + zeros the acts row. Values come from exact_vals_kernel.
// ---------------------------------------------------------------------------
#define TK_THREADS 256
#define TK_SMEM_BYTES ((DICT + 8 * 256) * 4)

__device__ __forceinline__ unsigned f2k(unsigned u) {
    return (u & 0x80000000u) ? ~u : (u | 0x80000000u);
}
__device__ __forceinline__ float k2f(unsigned k) {
    unsigned u = (k & 0x80000000u) ? (k ^ 0x80000000u) : ~k;
    return __uint_as_float(u);
}

__global__ __launch_bounds__(TK_THREADS) void topk_kernel(
    const float* __restrict__ x,
    const float* __restrict__ Wenc,
    float* __restrict__ acts)
{
    extern __shared__ unsigned sm[];
    unsigned* keys = sm;            // [DICT]
    unsigned* aux  = sm + DICT;     // 8KB: radix hists / x-row / fp64 reduce

    __shared__ unsigned s_need, s_sel, s_ns, s_nc;
    __shared__ int      cand_idx[64];
    __shared__ double   cand_score[64];
    __shared__ unsigned char chosen[64];

    const int tid = threadIdx.x;
    const int wid = tid >> 5;
    const int b   = blockIdx.x;
    const float* row  = g_pre + (size_t)b * DICT;
    float*       arow = acts  + (size_t)b * DICT;

    {   // monotone float->uint keys
        const uint4* row4 = (const uint4*)row;
        for (int i = tid; i < DICT / 4; i += TK_THREADS) {
            uint4 u = row4[i];
            uint4 kk;
            kk.x = f2k(u.x); kk.y = f2k(u.y); kk.z = f2k(u.z); kk.w = f2k(u.w);
            *(uint4*)&keys[i * 4] = kk;
        }
    }
    if (tid == 0) { s_need = TOPK; s_ns = 0; s_nc = 0; }
    __syncthreads();

    unsigned prefix = 0;
    for (int pass = 0; pass < 4; ++pass) {
        const int shift = 24 - 8 * pass;
        for (int i = tid; i < 8 * 256; i += TK_THREADS) aux[i] = 0;
        __syncthreads();
        const unsigned hi_mask = (pass == 0) ? 0u : (0xFFFFFFFFu << (shift + 8));
        for (int i = tid; i < DICT; i += TK_THREADS) {
            const unsigned key = keys[i];
            if ((key & hi_mask) == prefix)
                atomicAdd(&aux[(wid << 8) + ((key >> shift) & 255u)], 1u);
        }
        __syncthreads();
        unsigned cnt = 0;
        #pragma unroll
        for (int w = 0; w < 8; ++w) cnt += aux[(w << 8) + tid];
        aux[tid] = cnt;
        __syncthreads();
        if (tid == 0) {
            unsigned need = s_need, accum = 0;
            int sel = 0;
            for (int bkt = 255; bkt >= 0; --bkt) {
                const unsigned c = aux[bkt];
                if (accum + c >= need) { sel = bkt; break; }
                accum += c;
            }
            s_need = need - accum;
            s_sel  = (unsigned)sel;
        }
        __syncthreads();
        prefix |= (s_sel << shift);
    }
    const float Tv = k2f(prefix);    // coarse value of the 64th largest

    {   // zero the output acts row
        float4 z = make_float4(0.f, 0.f, 0.f, 0.f);
        float4* a4 = (float4*)arow;
        for (int i = tid; i < DICT / 4; i += TK_THREADS) a4[i] = z;
    }
    __syncthreads();

    const float hi = Tv + DELTA;
    const float lo = Tv - DELTA;
    for (int i = tid; i < DICT; i += TK_THREADS) {
        const float v = k2f(keys[i]);
        if (v > hi) {
            const unsigned slot = atomicAdd(&s_ns, 1u);
            g_cidx[b * TOPK + slot] = i;
        } else if (v >= lo) {
            const unsigned c = atomicAdd(&s_nc, 1u);
            if (c < 64u) cand_idx[c] = i;
        }
    }
    __syncthreads();

    const int ns   = (int)s_ns;
    const int need = TOPK - ns;
    const int nc   = (int)min(s_nc, 64u);

    if (nc <= need) {
        for (int j = tid; j < nc; j += TK_THREADS)
            g_cidx[b * TOPK + ns + j] = cand_idx[j];
        return;
    }

    // exact fp64 rescoring of candidates (b_enc == 0 by construction)
    float*  xs  = (float*)aux;                 // 768 floats
    double* red = (double*)(aux + 1024);       // 256 doubles
    for (int d = tid; d < D_MODEL; d += TK_THREADS)
        xs[d] = x[(size_t)b * D_MODEL + d];
    __syncthreads();

    for (int c = 0; c < nc; ++c) {
        const float* wr = Wenc + (size_t)cand_idx[c] * D_MODEL;
        double p = 0.0;
        for (int d = tid; d < D_MODEL; d += TK_THREADS)
            p += (double)xs[d] * (double)wr[d];
        red[tid] = p;
        __syncthreads();
        for (int s = TK_THREADS / 2; s > 0; s >>= 1) {
            if (tid < s) red[tid] += red[tid + s];
            __syncthreads();
        }
        if (tid == 0) cand_score[c] = red[0];
        __syncthreads();
    }

    if (tid == 0) {
        for (int c = 0; c < nc; ++c) chosen[c] = 0;
        int slot = ns;
        for (int n = 0; n < need; ++n) {
            int best = -1;
            for (int c = 0; c < nc; ++c) {
                if (chosen[c]) continue;
                if (best < 0 ||
                    cand_score[c] > cand_score[best] ||
                    (cand_score[c] == cand_score[best] && cand_idx[c] < cand_idx[best]))
                    best = c;
            }
            chosen[best] = 1;
            g_cidx[b * TOPK + slot] = cand_idx[best];
            ++slot;
        }
    }
}

// ---------------------------------------------------------------------------
// K3b: exact fp32 values for the 64 selected features per row.
// One CTA per row; each warp handles 8 features (coalesced W_enc row reads).
// ---------------------------------------------------------------------------
__global__ __launch_bounds__(256) void exact_vals_kernel(
    const float* __restrict__ x,
    const float* __restrict__ Wenc,
    const float* __restrict__ bias,
    float* __restrict__ acts)
{
    __shared__ float xs[D_MODEL];
    const int tid  = threadIdx.x;
    const int lane = tid & 31;
    const int wid  = tid >> 5;
    const int b    = blockIdx.x;

    const float4* xr = (const float4*)(x + (size_t)b * D_MODEL);
    for (int i = tid; i < D_MODEL / 4; i += 256) ((float4*)xs)[i] = xr[i];
    __syncthreads();

    for (int j = wid; j < TOPK; j += 8) {
        const int f = g_cidx[b * TOPK + j];
        const float4* wr = (const float4*)(Wenc + (size_t)f * D_MODEL);
        float s = 0.0f;
        #pragma unroll 6
        for (int i = lane; i < D_MODEL / 4; i += 32) {
            const float4 w  = wr[i];
            const float4 xv = ((const float4*)xs)[i];
            s += w.x * xv.x + w.y * xv.y + w.z * xv.z + w.w * xv.w;
        }
        #pragma unroll
        for (int o = 16; o > 0; o >>= 1)
            s += __shfl_xor_sync(0xffffffffu, s, o);
        if (lane == 0) {
            const float rv = fmaxf(s + bias[f], 0.0f);
            g_cval[b * TOPK + j] = rv;
            acts[(size_t)b * DICT + f] = rv;
        }
    }
}

// ---------------------------------------------------------------------------
// K4: sparse decoder  recon[b,:] = sum_{j<64} val_j * W_decT[idx_j, :]
// ---------------------------------------------------------------------------
__global__ __launch_bounds__(256) void dec_kernel(float* __restrict__ recon)
{
    __shared__ int   sidx[TOPK];
    __shared__ float sval[TOPK];
    const int tid = threadIdx.x;
    const int b   = blockIdx.x;

    if (tid < TOPK) {
        sidx[tid] = g_cidx[b * TOPK + tid];
        sval[tid] = g_cval[b * TOPK + tid];
    }
    __syncthreads();

    float acc0 = 0.0f, acc1 = 0.0f, acc2 = 0.0f;
    const int d0 = tid, d1 = tid + 256, d2 = tid + 512;
    #pragma unroll 4
    for (int j = 0; j < TOPK; ++j) {
        const float* wr = g_wdecT + (size_t)sidx[j] * D_MODEL;
        const float  v  = sval[j];
        acc0 += v * wr[d0];
        acc1 += v * wr[d1];
        acc2 += v * wr[d2];
    }
    float* orow = recon + (size_t)b * D_MODEL;
    orow[d0] = acc0;
    orow[d1] = acc1;
    orow[d2] = acc2;
}

// ---------------------------------------------------------------------------
// Launch: out = [recon (B*D_MODEL) | acts (B*DICT)] fp32
// ---------------------------------------------------------------------------
extern "C" void kernel_launch(void* const* d_in, const int* in_sizes, int n_in,
                              void* d_out, int out_size)
{
    const float* x     = (const float*)d_in[0];
    const float* W_enc = (const float*)d_in[1];
    const float* b_enc = (const float*)d_in[2];
    const float* W_dec = (const float*)d_in[3];
    (void)in_sizes; (void)n_in; (void)out_size;   // k hardcoded to 64

    float* recon = (float*)d_out;
    float* acts  = (float*)d_out + (size_t)B_ROWS * D_MODEL;

    cudaFuncSetAttribute(tf32_gemm_kernel,
                         cudaFuncAttributeMaxDynamicSharedMemorySize,
                         GEMM_SMEM_BYTES);
    cudaFuncSetAttribute(topk_kernel,
                         cudaFuncAttributeMaxDynamicSharedMemorySize,
                         TK_SMEM_BYTES);

    transpose_kernel<<<dim3(DICT / 32, D_MODEL / 32), dim3(32, 8)>>>(W_dec);
    tf32_gemm_kernel<<<dim3(DICT / 128, B_ROWS / 128), 256, GEMM_SMEM_BYTES>>>(
        x, W_enc, b_enc);
    topk_kernel<<<B_ROWS, TK_THREADS, TK_SMEM_BYTES>>>(x, W_enc, acts);
    exact_vals_kernel<<<B_ROWS, 256>>>(x, W_enc, b_enc, acts);
    dec_kernel<<<B_ROWS, 256>>>(recon);
}

// round 7
// speedup vs baseline: 3.8477x; 1.5434x over previous
#include <cuda_runtime.h>
#include <cuda_fp16.h>
#include <cstdint>

// Problem constants
#define B_ROWS  4096
#define D_MODEL 768
#define DICT    24576
#define TOPK    64
#define DELTA   0.01f   // window: ~7 sigma of (fp16 mma + fp16 storage) noise

// ---------------------------------------------------------------------------
// Scratch (static __device__ globals: allocation-free per harness rules)
// ---------------------------------------------------------------------------
__device__ __half g_preh[(size_t)B_ROWS * DICT];    // 201 MB coarse scores
__device__ __half g_xh[(size_t)B_ROWS * D_MODEL];   // x in fp16
__device__ __half g_wh[(size_t)DICT * D_MODEL];     // W_enc in fp16
__device__ float  g_wdecT[(size_t)DICT * D_MODEL];  // transposed decoder
__device__ int    g_cidx[B_ROWS * TOPK];            // selected indices
__device__ float  g_cval[B_ROWS * TOPK];            // exact values (post-relu)

// ---------------------------------------------------------------------------
// PTX helpers
// ---------------------------------------------------------------------------
#define CPA16(dst, src) \
    asm volatile("cp.async.cg.shared.global [%0], [%1], 16;" :: "r"(dst), "l"(src))
#define CPA_COMMIT() asm volatile("cp.async.commit_group;" ::: "memory")
#define CPA_WAIT0()  asm volatile("cp.async.wait_group 0;" ::: "memory")

#define LDMX4(r, addr) \
    asm volatile("ldmatrix.sync.aligned.m8n8.x4.shared.b16 {%0,%1,%2,%3}, [%4];" \
        : "=r"((r)[0]), "=r"((r)[1]), "=r"((r)[2]), "=r"((r)[3]) : "r"(addr))

#define MMA_F16(acc, a, b0, b1) \
    asm volatile("mma.sync.aligned.m16n8k16.row.col.f32.f16.f16.f32 " \
        "{%0,%1,%2,%3}, {%4,%5,%6,%7}, {%8,%9}, {%0,%1,%2,%3};" \
        : "+f"((acc)[0]), "+f"((acc)[1]), "+f"((acc)[2]), "+f"((acc)[3]) \
        : "r"((a)[0]), "r"((a)[1]), "r"((a)[2]), "r"((a)[3]), "r"(b0), "r"(b1))

// ---------------------------------------------------------------------------
// K0: fp32 -> fp16 conversion (grid-stride, vectorized)
// ---------------------------------------------------------------------------
__global__ void cvt_kernel(const float* __restrict__ src, __half* __restrict__ dst,
                           int n4)
{
    const int i = blockIdx.x * blockDim.x + threadIdx.x;
    const int stride = gridDim.x * blockDim.x;
    for (int j = i; j < n4; j += stride) {
        const float4 v = ((const float4*)src)[j];
        __half2 h0 = __floats2half2_rn(v.x, v.y);
        __half2 h1 = __floats2half2_rn(v.z, v.w);
        ((uint2*)dst)[j] = make_uint2(*(uint32_t*)&h0, *(uint32_t*)&h1);
    }
}

// ---------------------------------------------------------------------------
// K1: transpose W_dec [D_MODEL, DICT] -> W_decT [DICT, D_MODEL]
// ---------------------------------------------------------------------------
__global__ void transpose_kernel(const float* __restrict__ W)
{
    __shared__ float tile[32][33];
    const int tx = threadIdx.x, ty = threadIdx.y;
    const int x = blockIdx.x * 32 + tx;
    const int y = blockIdx.y * 32 + ty;

    #pragma unroll
    for (int r = 0; r < 32; r += 8)
        tile[ty + r][tx] = W[(size_t)(y + r) * DICT + x];
    __syncthreads();

    const int xo = blockIdx.y * 32 + tx;
    const int yo = blockIdx.x * 32 + ty;
    #pragma unroll
    for (int r = 0; r < 32; r += 8)
        g_wdecT[(size_t)(yo + r) * D_MODEL + xo] = tile[tx][ty + r];
}

// ---------------------------------------------------------------------------
// K2: fp16 tensor-core GEMM  pre[b,f] = sum_d x[b,d]*W_enc[f,d] + b_enc[f]
// CTA tile 128x128, BK=64 (fp16), 8 warps (4M x 2N), m16n8k16.
// smem: A[2][128][64h] + B[2][128][64h], 128B rows, XOR-16B swizzle,
// cp.async double buffered. Same byte geometry as the validated tf32 kernel.
// ---------------------------------------------------------------------------
#define GEMM_SMEM_BYTES 65536

__global__ __launch_bounds__(256, 2) void hgemm_kernel(
    const float* __restrict__ bias)
{
    extern __shared__ __half smem[];
    const int tid  = threadIdx.x;
    const int lane = tid & 31;
    const int wid  = tid >> 5;
    const int wm   = wid & 3;            // M warp: 32*wm
    const int wn   = wid >> 2;           // N warp: 64*wn
    const int bF   = blockIdx.x * 128;
    const int bB   = blockIdx.y * 128;

    const uint32_t sbase = (uint32_t)__cvta_generic_to_shared(smem);
    const uint32_t sA = sbase;           // stage stride 16384 B
    const uint32_t sB = sbase + 32768;

    // loaders: 128 rows x 128B per tile; thread -> 4 chunks of 16B
    const int lrow = tid >> 3;           // 0..31
    const int lc16 = tid & 7;            // 0..7
    const __half* gA = g_xh + (size_t)(bB + lrow) * D_MODEL + lc16 * 8;
    const __half* gB = g_wh + (size_t)(bF + lrow) * D_MODEL + lc16 * 8;
    uint32_t dOff[4];
    #pragma unroll
    for (int j = 0; j < 4; ++j) {
        const int r = lrow + 32 * j;
        dOff[j] = (uint32_t)(r * 128 + ((lc16 * 16) ^ ((r & 7) << 4)));
    }

    // ldmatrix addressing (identical byte pattern to tf32 version)
    const int mat  = lane >> 3;
    const int mrow = lane & 7;
    const int aRow0   = wm * 32 + (mat & 1) * 8 + mrow;
    const uint32_t aX = (uint32_t)((aRow0 & 7) << 4);
    const int aKh     = mat >> 1;        // k half (8 fp16 = 16B)
    const int bRow0   = wn * 64 + (mat >> 1) * 8 + mrow;
    const uint32_t bX = (uint32_t)((bRow0 & 7) << 4);
    const int bKh     = mat & 1;

    float acc[2][8][4];
    #pragma unroll
    for (int tm = 0; tm < 2; ++tm)
        #pragma unroll
        for (int tn = 0; tn < 8; ++tn)
            #pragma unroll
            for (int q = 0; q < 4; ++q) acc[tm][tn][q] = 0.0f;

    #pragma unroll
    for (int j = 0; j < 4; ++j) {
        CPA16(sA + dOff[j], gA + (size_t)(32 * j) * D_MODEL);
        CPA16(sB + dOff[j], gB + (size_t)(32 * j) * D_MODEL);
    }
    CPA_COMMIT();
    CPA_WAIT0();
    __syncthreads();

    const int NKT = D_MODEL / 64;        // 12
    for (int kt = 0; kt < NKT; ++kt) {
        const uint32_t cur = (kt & 1) * 16384u;
        const uint32_t nxt = 16384u - cur;
        if (kt + 1 < NKT) {
            const int ko = (kt + 1) * 64;
            #pragma unroll
            for (int j = 0; j < 4; ++j) {
                CPA16(sA + nxt + dOff[j], gA + (size_t)(32 * j) * D_MODEL + ko);
                CPA16(sB + nxt + dOff[j], gB + (size_t)(32 * j) * D_MODEL + ko);
            }
            CPA_COMMIT();
        }

        #pragma unroll
        for (int ks = 0; ks < 4; ++ks) {    // 16 fp16 (32B) per step
            uint32_t a0[4], a1[4], bf[4][4];
            const uint32_t aK = ((uint32_t)(ks << 5) | (uint32_t)(aKh << 4)) ^ aX;
            const uint32_t bK = ((uint32_t)(ks << 5) | (uint32_t)(bKh << 4)) ^ bX;
            LDMX4(a0, sA + cur + (uint32_t)(aRow0 * 128) + aK);
            LDMX4(a1, sA + cur + (uint32_t)((aRow0 + 16) * 128) + aK);
            #pragma unroll
            for (int p = 0; p < 4; ++p)
                LDMX4(bf[p], sB + cur + (uint32_t)((bRow0 + p * 16) * 128) + bK);

            #pragma unroll
            for (int tn = 0; tn < 8; ++tn) {
                const int p  = tn >> 1;
                const int i0 = (tn & 1) * 2;
                MMA_F16(acc[0][tn], a0, bf[p][i0], bf[p][i0 + 1]);
                MMA_F16(acc[1][tn], a1, bf[p][i0], bf[p][i0 + 1]);
            }
        }

        if (kt + 1 < NKT) CPA_WAIT0();
        __syncthreads();
    }

    // epilogue: add bias, store coarse scores as fp16
    const int g  = lane >> 2;
    const int tg = lane & 3;
    #pragma unroll
    for (int tn = 0; tn < 8; ++tn) {
        const int col = bF + wn * 64 + tn * 8 + tg * 2;
        const float2 bv = *(const float2*)(bias + col);
        #pragma unroll
        for (int tm = 0; tm < 2; ++tm) {
            const int r0 = bB + wm * 32 + tm * 16 + g;
            __half2 h0 = __floats2half2_rn(acc[tm][tn][0] + bv.x,
                                           acc[tm][tn][1] + bv.y);
            __half2 h1 = __floats2half2_rn(acc[tm][tn][2] + bv.x,
                                           acc[tm][tn][3] + bv.y);
            *(__half2*)&g_preh[(size_t)r0 * DICT + col]       = h0;
            *(__half2*)&g_preh[(size_t)(r0 + 8) * DICT + col] = h1;
        }
    }
}

// ---------------------------------------------------------------------------
// K3: per-row top-64 on fp16 coarse scores.
//  a) 2-pass 8-bit radix select on 16-bit monotone keys -> coarse 64th Tv
//  b) sure-in: v > Tv+DELTA; candidates |v-Tv| <= DELTA
//  c) fp64 rescore of candidates when they exceed open slots
// ---------------------------------------------------------------------------
#define TK_THREADS 256
#define TK_SMEM_BYTES (DICT * 2 + 8 * 256 * 4)   // 48KB keys + 8KB aux

__device__ __forceinline__ float k2f16(unsigned k) {
    const unsigned u = (k & 0x8000u) ? (k ^ 0x8000u) : ((~k) & 0xFFFFu);
    __half_raw hr; hr.x = (unsigned short)u;
    return __half2float(hr);
}

__global__ __launch_bounds__(TK_THREADS) void topk_kernel(
    const float* __restrict__ x,
    const float* __restrict__ Wenc,
    const float* __restrict__ bias,
    float* __restrict__ acts)
{
    extern __shared__ unsigned sm[];
    unsigned short* keys = (unsigned short*)sm;        // [DICT] 48KB
    unsigned*       aux  = sm + DICT / 2;              // 8KB

    __shared__ unsigned s_need, s_sel, s_ns, s_nc;
    __shared__ int      cand_idx[64];
    __shared__ double   cand_score[64];
    __shared__ unsigned char chosen[64];

    const int tid = threadIdx.x;
    const int wid = tid >> 5;
    const int b   = blockIdx.x;
    const __half* row  = g_preh + (size_t)b * DICT;
    float*        arow = acts   + (size_t)b * DICT;

    // monotone 16-bit keys, 8 per 16B load
    {
        const uint4* row8 = (const uint4*)row;
        for (int i = tid; i < DICT / 8; i += TK_THREADS) {
            const uint4 u = row8[i];
            uint32_t w[4] = {u.x, u.y, u.z, u.w};
            uint32_t o[4];
            #pragma unroll
            for (int q = 0; q < 4; ++q) {
                uint32_t lo = w[q] & 0xFFFFu, hi = w[q] >> 16;
                lo = (lo & 0x8000u) ? ((~lo) & 0xFFFFu) : (lo | 0x8000u);
                hi = (hi & 0x8000u) ? ((~hi) & 0xFFFFu) : (hi | 0x8000u);
                o[q] = lo | (hi << 16);
            }
            ((uint4*)keys)[i] = make_uint4(o[0], o[1], o[2], o[3]);
        }
    }
    if (tid == 0) { s_need = TOPK; s_ns = 0; s_nc = 0; }
    __syncthreads();

    // ---- 2-pass radix select ----
    unsigned prefix = 0;   // after pass0: selected high byte
    for (int pass = 0; pass < 2; ++pass) {
        for (int i = tid; i < 8 * 256; i += TK_THREADS) aux[i] = 0;
        __syncthreads();
        if (pass == 0) {
            for (int i = tid; i < DICT; i += TK_THREADS)
                atomicAdd(&aux[(wid << 8) + (keys[i] >> 8)], 1u);
        } else {
            for (int i = tid; i < DICT; i += TK_THREADS) {
                const unsigned key = keys[i];
                if ((key >> 8) == prefix)
                    atomicAdd(&aux[(wid << 8) + (key & 255u)], 1u);
            }
        }
        __syncthreads();
        unsigned cnt = 0;
        #pragma unroll
        for (int w = 0; w < 8; ++w) cnt += aux[(w << 8) + tid];
        aux[tid] = cnt;
        __syncthreads();
        if (tid == 0) {
            unsigned need = s_need, accum = 0;
            int sel = 0;
            for (int bkt = 255; bkt >= 0; --bkt) {
                const unsigned c = aux[bkt];
                if (accum + c >= need) { sel = bkt; break; }
                accum += c;
            }
            s_need = need - accum;
            s_sel  = (unsigned)sel;
        }
        __syncthreads();
        prefix = (pass == 0) ? s_sel : ((prefix << 8) | s_sel);
        __syncthreads();
    }
    const float Tv = k2f16(prefix);   // coarse value of the 64th largest

    // zero the acts output row (fp32)
    {
        float4 z = make_float4(0.f, 0.f, 0.f, 0.f);
        float4* a4 = (float4*)arow;
        for (int i = tid; i < DICT / 4; i += TK_THREADS) a4[i] = z;
    }
    __syncthreads();

    const float hi = Tv + DELTA;
    const float lo = Tv - DELTA;
    for (int i = tid; i < DICT; i += TK_THREADS) {
        const float v = k2f16(keys[i]);
        if (v > hi) {
            const unsigned slot = atomicAdd(&s_ns, 1u);
            g_cidx[b * TOPK + slot] = i;
        } else if (v >= lo) {
            const unsigned c = atomicAdd(&s_nc, 1u);
            if (c < 64u) cand_idx[c] = i;
        }
    }
    __syncthreads();

    const int ns   = (int)s_ns;
    const int need = TOPK - ns;
    const int nc   = (int)min(s_nc, 64u);

    if (nc <= need) {
        for (int j = tid; j < nc; j += TK_THREADS)
            g_cidx[b * TOPK + ns + j] = cand_idx[j];
        return;
    }

    // exact fp64 rescoring of candidates
    float*  xs  = (float*)aux;                 // 768 floats
    double* red = (double*)(aux + 1024);       // 256 doubles
    for (int d = tid; d < D_MODEL; d += TK_THREADS)
        xs[d] = x[(size_t)b * D_MODEL + d];
    __syncthreads();

    for (int c = 0; c < nc; ++c) {
        const float* wr = Wenc + (size_t)cand_idx[c] * D_MODEL;
        double p = 0.0;
        for (int d = tid; d < D_MODEL; d += TK_THREADS)
            p += (double)xs[d] * (double)wr[d];
        red[tid] = p;
        __syncthreads();
        for (int s = TK_THREADS / 2; s > 0; s >>= 1) {
            if (tid < s) red[tid] += red[tid + s];
            __syncthreads();
        }
        if (tid == 0) cand_score[c] = red[0] + (double)bias[cand_idx[c]];
        __syncthreads();
    }

    if (tid == 0) {
        for (int c = 0; c < nc; ++c) chosen[c] = 0;
        int slot = ns;
        for (int n = 0; n < need; ++n) {
            int best = -1;
            for (int c = 0; c < nc; ++c) {
                if (chosen[c]) continue;
                if (best < 0 ||
                    cand_score[c] > cand_score[best] ||
                    (cand_score[c] == cand_score[best] && cand_idx[c] < cand_idx[best]))
                    best = c;
            }
            chosen[best] = 1;
            g_cidx[b * TOPK + slot] = cand_idx[best];
            ++slot;
        }
    }
}

// ---------------------------------------------------------------------------
// K3b: exact fp32 values for the 64 selected features per row.
// ---------------------------------------------------------------------------
__global__ __launch_bounds__(256) void exact_vals_kernel(
    const float* __restrict__ x,
    const float* __restrict__ Wenc,
    const float* __restrict__ bias,
    float* __restrict__ acts)
{
    __shared__ float xs[D_MODEL];
    const int tid  = threadIdx.x;
    const int lane = tid & 31;
    const int wid  = tid >> 5;
    const int b    = blockIdx.x;

    const float4* xr = (const float4*)(x + (size_t)b * D_MODEL);
    for (int i = tid; i < D_MODEL / 4; i += 256) ((float4*)xs)[i] = xr[i];
    __syncthreads();

    for (int j = wid; j < TOPK; j += 8) {
        const int f = g_cidx[b * TOPK + j];
        const float4* wr = (const float4*)(Wenc + (size_t)f * D_MODEL);
        float s = 0.0f;
        #pragma unroll 6
        for (int i = lane; i < D_MODEL / 4; i += 32) {
            const float4 w  = wr[i];
            const float4 xv = ((const float4*)xs)[i];
            s += w.x * xv.x + w.y * xv.y + w.z * xv.z + w.w * xv.w;
        }
        #pragma unroll
        for (int o = 16; o > 0; o >>= 1)
            s += __shfl_xor_sync(0xffffffffu, s, o);
        if (lane == 0) {
            const float rv = fmaxf(s + bias[f], 0.0f);
            g_cval[b * TOPK + j] = rv;
            acts[(size_t)b * DICT + f] = rv;
        }
    }
}

// ---------------------------------------------------------------------------
// K4: sparse decoder  recon[b,:] = sum_{j<64} val_j * W_decT[idx_j, :]
// ---------------------------------------------------------------------------
__global__ __launch_bounds__(256) void dec_kernel(float* __restrict__ recon)
{
    __shared__ int   sidx[TOPK];
    __shared__ float sval[TOPK];
    const int tid = threadIdx.x;
    const int b   = blockIdx.x;

    if (tid < TOPK) {
        sidx[tid] = g_cidx[b * TOPK + tid];
        sval[tid] = g_cval[b * TOPK + tid];
    }
    __syncthreads();

    float acc0 = 0.0f, acc1 = 0.0f, acc2 = 0.0f;
    const int d0 = tid, d1 = tid + 256, d2 = tid + 512;
    #pragma unroll 4
    for (int j = 0; j < TOPK; ++j) {
        const float* wr = g_wdecT + (size_t)sidx[j] * D_MODEL;
        const float  v  = sval[j];
        acc0 += v * wr[d0];
        acc1 += v * wr[d1];
        acc2 += v * wr[d2];
    }
    float* orow = recon + (size_t)b * D_MODEL;
    orow[d0] = acc0;
    orow[d1] = acc1;
    orow[d2] = acc2;
}

// ---------------------------------------------------------------------------
// Launch: out = [recon (B*D_MODEL) | acts (B*DICT)] fp32
// ---------------------------------------------------------------------------
extern "C" void kernel_launch(void* const* d_in, const int* in_sizes, int n_in,
                              void* d_out, int out_size)
{
    const float* x     = (const float*)d_in[0];
    const float* W_enc = (const float*)d_in[1];
    const float* b_enc = (const float*)d_in[2];
    const float* W_dec = (const float*)d_in[3];
    (void)in_sizes; (void)n_in; (void)out_size;   // k hardcoded to 64

    float* recon = (float*)d_out;
    float* acts  = (float*)d_out + (size_t)B_ROWS * D_MODEL;

    cudaFuncSetAttribute(hgemm_kernel,
                         cudaFuncAttributeMaxDynamicSharedMemorySize,
                         GEMM_SMEM_BYTES);
    cudaFuncSetAttribute(topk_kernel,
                         cudaFuncAttributeMaxDynamicSharedMemorySize,
                         TK_SMEM_BYTES);

    __half* xh; cudaGetSymbolAddress((void**)&xh, g_xh);
    __half* wh; cudaGetSymbolAddress((void**)&wh, g_wh);

    cvt_kernel<<<256, 256>>>(x,     xh, B_ROWS * D_MODEL / 4);
    cvt_kernel<<<1024, 256>>>(W_enc, wh, DICT * D_MODEL / 4);
    transpose_kernel<<<dim3(DICT / 32, D_MODEL / 32), dim3(32, 8)>>>(W_dec);
    hgemm_kernel<<<dim3(DICT / 128, B_ROWS / 128), 256, GEMM_SMEM_BYTES>>>(b_enc);
    topk_kernel<<<B_ROWS, TK_THREADS, TK_SMEM_BYTES>>>(x, W_enc, b_enc, acts);
    exact_vals_kernel<<<B_ROWS, 256>>>(x, W_enc, b_enc, acts);
    dec_kernel<<<B_ROWS, 256>>>(recon);
}

// round 8
// speedup vs baseline: 4.0142x; 1.0433x over previous
#include <cuda_runtime.h>
#include <cuda_fp16.h>
#include <cstdint>

// Problem constants
#define B_ROWS  4096
#define D_MODEL 768
#define DICT    24576
#define TOPK    64
#define DELTA   0.01f   // window: ~7 sigma of (fp16 mma + fp16 storage) noise

// ---------------------------------------------------------------------------
// Scratch (static __device__ globals: allocation-free per harness rules)
// ---------------------------------------------------------------------------
__device__ unsigned short g_keys[(size_t)B_ROWS * DICT]; // monotone u16 coarse keys
__device__ __half g_xh[(size_t)B_ROWS * D_MODEL];        // x in fp16
__device__ __half g_wh[(size_t)DICT * D_MODEL];          // W_enc in fp16
__device__ float  g_wdecT[(size_t)DICT * D_MODEL];       // transposed decoder
__device__ int    g_cidx[B_ROWS * TOPK];                 // selected indices

// ---------------------------------------------------------------------------
// PTX helpers
// ---------------------------------------------------------------------------
#define CPA16(dst, src) \
    asm volatile("cp.async.cg.shared.global [%0], [%1], 16;" :: "r"(dst), "l"(src))
#define CPA_COMMIT() asm volatile("cp.async.commit_group;" ::: "memory")
#define CPA_WAIT0()  asm volatile("cp.async.wait_group 0;" ::: "memory")
#define CPA_WAIT1()  asm volatile("cp.async.wait_group 1;" ::: "memory")

#define LDMX4(r, addr) \
    asm volatile("ldmatrix.sync.aligned.m8n8.x4.shared.b16 {%0,%1,%2,%3}, [%4];" \
        : "=r"((r)[0]), "=r"((r)[1]), "=r"((r)[2]), "=r"((r)[3]) : "r"(addr))

#define MMA_F16(acc, a, b0, b1) \
    asm volatile("mma.sync.aligned.m16n8k16.row.col.f32.f16.f16.f32 " \
        "{%0,%1,%2,%3}, {%4,%5,%6,%7}, {%8,%9}, {%0,%1,%2,%3};" \
        : "+f"((acc)[0]), "+f"((acc)[1]), "+f"((acc)[2]), "+f"((acc)[3]) \
        : "r"((a)[0]), "r"((a)[1]), "r"((a)[2]), "r"((a)[3]), "r"(b0), "r"(b1))

// ---------------------------------------------------------------------------
// K0: fp32 -> fp16 conversion (grid-stride, vectorized)
// ---------------------------------------------------------------------------
__global__ void cvt_kernel(const float* __restrict__ src, __half* __restrict__ dst,
                           int n4)
{
    const int i = blockIdx.x * blockDim.x + threadIdx.x;
    const int stride = gridDim.x * blockDim.x;
    for (int j = i; j < n4; j += stride) {
        const float4 v = ((const float4*)src)[j];
        __half2 h0 = __floats2half2_rn(v.x, v.y);
        __half2 h1 = __floats2half2_rn(v.z, v.w);
        ((uint2*)dst)[j] = make_uint2(*(uint32_t*)&h0, *(uint32_t*)&h1);
    }
}

// ---------------------------------------------------------------------------
// K1: transpose W_dec [D_MODEL, DICT] -> W_decT [DICT, D_MODEL]
// ---------------------------------------------------------------------------
__global__ void transpose_kernel(const float* __restrict__ W)
{
    __shared__ float tile[32][33];
    const int tx = threadIdx.x, ty = threadIdx.y;
    const int x = blockIdx.x * 32 + tx;
    const int y = blockIdx.y * 32 + ty;

    #pragma unroll
    for (int r = 0; r < 32; r += 8)
        tile[ty + r][tx] = W[(size_t)(y + r) * DICT + x];
    __syncthreads();

    const int xo = blockIdx.y * 32 + tx;
    const int yo = blockIdx.x * 32 + ty;
    #pragma unroll
    for (int r = 0; r < 32; r += 8)
        g_wdecT[(size_t)(yo + r) * D_MODEL + xo] = tile[tx][ty + r];
}

// ---------------------------------------------------------------------------
// K2: fp16 tensor-core GEMM, 3-stage cp.async pipeline.
// CTA tile 128x128, BK=64, 8 warps (4M x 2N), m16n8k16.
// Stage layout: stage s at s*32768; A tile at +0 (16KB), B tile at +16384.
// Epilogue writes monotone u16 keys of half(pre_act) straight to g_keys.
// ---------------------------------------------------------------------------
#define GEMM_SMEM_BYTES (3 * 32768)

__global__ __launch_bounds__(256, 2) void hgemm_kernel(
    const float* __restrict__ bias)
{
    extern __shared__ __half smem[];
    const int tid  = threadIdx.x;
    const int lane = tid & 31;
    const int wid  = tid >> 5;
    const int wm   = wid & 3;            // M warp: 32*wm
    const int wn   = wid >> 2;           // N warp: 64*wn
    const int bF   = blockIdx.x * 128;
    const int bB   = blockIdx.y * 128;

    const uint32_t sbase = (uint32_t)__cvta_generic_to_shared(smem);

    // loaders: 128 rows x 128B per tile; thread -> 4 chunks of 16B
    const int lrow = tid >> 3;           // 0..31
    const int lc16 = tid & 7;            // 0..7
    const __half* gA = g_xh + (size_t)(bB + lrow) * D_MODEL + lc16 * 8;
    const __half* gB = g_wh + (size_t)(bF + lrow) * D_MODEL + lc16 * 8;
    uint32_t dOff[4];
    #pragma unroll
    for (int j = 0; j < 4; ++j) {
        const int r = lrow + 32 * j;
        dOff[j] = (uint32_t)(r * 128 + ((lc16 * 16) ^ ((r & 7) << 4)));
    }

    auto issue = [&](int stage, int kt) {
        const uint32_t sb = sbase + (uint32_t)stage * 32768u;
        const int ko = kt * 64;
        #pragma unroll
        for (int j = 0; j < 4; ++j) {
            CPA16(sb + dOff[j],          gA + (size_t)(32 * j) * D_MODEL + ko);
            CPA16(sb + 16384u + dOff[j], gB + (size_t)(32 * j) * D_MODEL + ko);
        }
        CPA_COMMIT();
    };

    // ldmatrix addressing
    const int mat  = lane >> 3;
    const int mrow = lane & 7;
    const int aRow0   = wm * 32 + (mat & 1) * 8 + mrow;
    const uint32_t aX = (uint32_t)((aRow0 & 7) << 4);
    const int aKh     = mat >> 1;        // 16B k-half
    const int bRow0   = wn * 64 + (mat >> 1) * 8 + mrow;
    const uint32_t bX = (uint32_t)((bRow0 & 7) << 4);
    const int bKh     = mat & 1;

    float acc[2][8][4];
    #pragma unroll
    for (int tm = 0; tm < 2; ++tm)
        #pragma unroll
        for (int tn = 0; tn < 8; ++tn)
            #pragma unroll
            for (int q = 0; q < 4; ++q) acc[tm][tn][q] = 0.0f;

    const int NKT = D_MODEL / 64;        // 12
    issue(0, 0);
    issue(1, 1);

    for (int kt = 0; kt < NKT; ++kt) {
        if (kt + 1 < NKT) { CPA_WAIT1(); } else { CPA_WAIT0(); }
        __syncthreads();

        const uint32_t cur = sbase + (uint32_t)(kt % 3) * 32768u;
        #pragma unroll
        for (int ks = 0; ks < 4; ++ks) {    // 16 fp16 (32B) per step
            uint32_t a0[4], a1[4], bf[4][4];
            const uint32_t aK = ((uint32_t)(ks << 5) | (uint32_t)(aKh << 4)) ^ aX;
            const uint32_t bK = ((uint32_t)(ks << 5) | (uint32_t)(bKh << 4)) ^ bX;
            LDMX4(a0, cur + (uint32_t)(aRow0 * 128) + aK);
            LDMX4(a1, cur + (uint32_t)((aRow0 + 16) * 128) + aK);
            #pragma unroll
            for (int p = 0; p < 4; ++p)
                LDMX4(bf[p], cur + 16384u + (uint32_t)((bRow0 + p * 16) * 128) + bK);

            #pragma unroll
            for (int tn = 0; tn < 8; ++tn) {
                const int p  = tn >> 1;
                const int i0 = (tn & 1) * 2;
                MMA_F16(acc[0][tn], a0, bf[p][i0], bf[p][i0 + 1]);
                MMA_F16(acc[1][tn], a1, bf[p][i0], bf[p][i0 + 1]);
            }
        }

        if (kt + 2 < NKT) issue((kt + 2) % 3, kt + 2);
    }

    // epilogue: add bias, convert to fp16, store monotone u16 keys
    auto mkey = [](float v) -> unsigned {
        const unsigned short us = __half_as_ushort(__float2half_rn(v));
        return (us & 0x8000u) ? (unsigned)((~us) & 0xFFFFu)
                              : (unsigned)(us | 0x8000u);
    };
    const int g  = lane >> 2;
    const int tg = lane & 3;
    #pragma unroll
    for (int tn = 0; tn < 8; ++tn) {
        const int col = bF + wn * 64 + tn * 8 + tg * 2;
        const float2 bv = *(const float2*)(bias + col);
        #pragma unroll
        for (int tm = 0; tm < 2; ++tm) {
            const int r0 = bB + wm * 32 + tm * 16 + g;
            const unsigned k0 = mkey(acc[tm][tn][0] + bv.x);
            const unsigned k1 = mkey(acc[tm][tn][1] + bv.y);
            const unsigned k2 = mkey(acc[tm][tn][2] + bv.x);
            const unsigned k3 = mkey(acc[tm][tn][3] + bv.y);
            *(unsigned*)&g_keys[(size_t)r0 * DICT + col]       = k0 | (k1 << 16);
            *(unsigned*)&g_keys[(size_t)(r0 + 8) * DICT + col] = k2 | (k3 << 16);
        }
    }
}

// ---------------------------------------------------------------------------
// K3: per-row top-64 on u16 monotone keys (already built by GEMM epilogue).
//  a) fused copy-to-smem + pass0 histogram; pass1 -> coarse 64th value Tv
//  b) fused zero-write + classify: sure-in (v > Tv+DELTA), candidates in window
//  c) fp64 rescore of candidates when they exceed open slots
// ---------------------------------------------------------------------------
#define TK_THREADS 512
#define TK_SMEM_BYTES (DICT * 2 + 8 * 256 * 4)   // 48KB keys + 8KB aux

__device__ __forceinline__ float k2f16(unsigned k) {
    const unsigned u = (k & 0x8000u) ? (k ^ 0x8000u) : ((~k) & 0xFFFFu);
    __half_raw hr; hr.x = (unsigned short)u;
    return __half2float(hr);
}

__global__ __launch_bounds__(TK_THREADS) void topk_kernel(
    const float* __restrict__ x,
    const float* __restrict__ Wenc,
    const float* __restrict__ bias,
    float* __restrict__ acts)
{
    extern __shared__ unsigned sm[];
    unsigned short* keys = (unsigned short*)sm;        // [DICT] 48KB
    unsigned*       aux  = sm + DICT / 2;              // 8KB

    __shared__ unsigned s_need, s_sel, s_ns, s_nc;
    __shared__ int      cand_idx[64];
    __shared__ double   cand_score[64];
    __shared__ unsigned char chosen[64];

    const int tid = threadIdx.x;
    const int w8  = (tid >> 5) & 7;
    const int b   = blockIdx.x;
    const unsigned short* row = g_keys + (size_t)b * DICT;
    float* arow = acts + (size_t)b * DICT;

    if (tid == 0) { s_need = TOPK; s_ns = 0; s_nc = 0; }
    for (int i = tid; i < 8 * 256; i += TK_THREADS) aux[i] = 0;
    __syncthreads();

    // ---- fused: copy keys to smem + pass0 histogram (high byte) ----
    {
        const uint4* row8 = (const uint4*)row;
        for (int i = tid; i < DICT / 8; i += TK_THREADS) {
            const uint4 u = row8[i];
            ((uint4*)keys)[i] = u;
            const uint32_t w[4] = {u.x, u.y, u.z, u.w};
            #pragma unroll
            for (int q = 0; q < 4; ++q) {
                atomicAdd(&aux[(w8 << 8) + ((w[q] & 0xFFFFu) >> 8)], 1u);
                atomicAdd(&aux[(w8 << 8) + (w[q] >> 24)], 1u);
            }
        }
    }
    __syncthreads();

    // ---- select high-byte bucket ----
    unsigned prefix;
    {
        if (tid < 256) {
            unsigned cnt = 0;
            #pragma unroll
            for (int w = 0; w < 8; ++w) cnt += aux[(w << 8) + tid];
            aux[tid] = cnt;
        }
        __syncthreads();
        if (tid == 0) {
            unsigned need = s_need, accum = 0;
            int sel = 0;
            for (int bkt = 255; bkt >= 0; --bkt) {
                const unsigned c = aux[bkt];
                if (accum + c >= need) { sel = bkt; break; }
                accum += c;
            }
            s_need = need - accum;
            s_sel  = (unsigned)sel;
        }
        __syncthreads();
        prefix = s_sel;
    }

    // ---- pass1: low byte within selected bucket ----
    __syncthreads();
    for (int i = tid; i < 8 * 256; i += TK_THREADS) aux[i] = 0;
    __syncthreads();
    for (int i = tid; i < DICT; i += TK_THREADS) {
        const unsigned key = keys[i];
        if ((key >> 8) == prefix)
            atomicAdd(&aux[(w8 << 8) + (key & 255u)], 1u);
    }
    __syncthreads();
    if (tid < 256) {
        unsigned cnt = 0;
        #pragma unroll
        for (int w = 0; w < 8; ++w) cnt += aux[(w << 8) + tid];
        aux[tid] = cnt;
    }
    __syncthreads();
    if (tid == 0) {
        unsigned need = s_need, accum = 0;
        int sel = 0;
        for (int bkt = 255; bkt >= 0; --bkt) {
            const unsigned c = aux[bkt];
            if (accum + c >= need) { sel = bkt; break; }
            accum += c;
        }
        s_sel = (prefix << 8) | (unsigned)sel;
    }
    __syncthreads();
    const float Tv = k2f16(s_sel);   // coarse value of the 64th largest

    // ---- fused: zero acts row + classify (4 keys / float4 zero per step) ----
    const float hi = Tv + DELTA;
    const float lo = Tv - DELTA;
    {
        const float4 z = make_float4(0.f, 0.f, 0.f, 0.f);
        const uint2* k4 = (const uint2*)keys;
        for (int i = tid; i < DICT / 4; i += TK_THREADS) {
            ((float4*)arow)[i] = z;
            const uint2 kk = k4[i];
            const unsigned ks[4] = {kk.x & 0xFFFFu, kk.x >> 16,
                                    kk.y & 0xFFFFu, kk.y >> 16};
            #pragma unroll
            for (int q = 0; q < 4; ++q) {
                const float v = k2f16(ks[q]);
                if (v > hi) {
                    const unsigned slot = atomicAdd(&s_ns, 1u);
                    g_cidx[b * TOPK + slot] = i * 4 + q;
                } else if (v >= lo) {
                    const unsigned c = atomicAdd(&s_nc, 1u);
                    if (c < 64u) cand_idx[c] = i * 4 + q;
                }
            }
        }
    }
    __syncthreads();

    const int ns   = (int)s_ns;
    const int need = TOPK - ns;
    const int nc   = (int)min(s_nc, 64u);

    if (nc <= need) {
        for (int j = tid; j < nc; j += TK_THREADS)
            g_cidx[b * TOPK + ns + j] = cand_idx[j];
        return;
    }

    // ---- exact fp64 rescoring of candidates ----
    float*  xs  = (float*)aux;                       // 3072B
    double* red = (double*)((char*)aux + 3072);      // 4096B (512 doubles)
    for (int d = tid; d < D_MODEL; d += TK_THREADS)
        xs[d] = x[(size_t)b * D_MODEL + d];
    __syncthreads();

    for (int c = 0; c < nc; ++c) {
        const float* wr = Wenc + (size_t)cand_idx[c] * D_MODEL;
        double p = 0.0;
        for (int d = tid; d < D_MODEL; d += TK_THREADS)
            p += (double)xs[d] * (double)wr[d];
        red[tid] = p;
        __syncthreads();
        for (int s = TK_THREADS / 2; s > 0; s >>= 1) {
            if (tid < s) red[tid] += red[tid + s];
            __syncthreads();
        }
        if (tid == 0) cand_score[c] = red[0] + (double)bias[cand_idx[c]];
        __syncthreads();
    }

    if (tid == 0) {
        for (int c = 0; c < nc; ++c) chosen[c] = 0;
        int slot = ns;
        for (int n = 0; n < need; ++n) {
            int best = -1;
            for (int c = 0; c < nc; ++c) {
                if (chosen[c]) continue;
                if (best < 0 ||
                    cand_score[c] > cand_score[best] ||
                    (cand_score[c] == cand_score[best] && cand_idx[c] < cand_idx[best]))
                    best = c;
            }
            chosen[best] = 1;
            g_cidx[b * TOPK + slot] = cand_idx[best];
            ++slot;
        }
    }
}

// ---------------------------------------------------------------------------
// K4: fused exact values + sparse decoder.
// Per row: 8 warps compute exact fp32 vals for 8 features each (into smem +
// scatter into acts), then all 256 threads run the sparse decoder from smem.
// ---------------------------------------------------------------------------
__global__ __launch_bounds__(256) void sparse_out_kernel(
    const float* __restrict__ x,
    const float* __restrict__ Wenc,
    const float* __restrict__ bias,
    float* __restrict__ acts,
    float* __restrict__ recon)
{
    __shared__ float xs[D_MODEL];
    __shared__ int   sidx[TOPK];
    __shared__ float sval[TOPK];
    const int tid  = threadIdx.x;
    const int lane = tid & 31;
    const int wid  = tid >> 5;
    const int b    = blockIdx.x;

    if (tid < TOPK) sidx[tid] = g_cidx[b * TOPK + tid];
    const float4* xr = (const float4*)(x + (size_t)b * D_MODEL);
    for (int i = tid; i < D_MODEL / 4; i += 256) ((float4*)xs)[i] = xr[i];
    __syncthreads();

    for (int j = wid; j < TOPK; j += 8) {
        const int f = sidx[j];
        const float4* wr = (const float4*)(Wenc + (size_t)f * D_MODEL);
        float s = 0.0f;
        #pragma unroll 6
        for (int i = lane; i < D_MODEL / 4; i += 32) {
            const float4 w  = wr[i];
            const float4 xv = ((const float4*)xs)[i];
            s += w.x * xv.x + w.y * xv.y + w.z * xv.z + w.w * xv.w;
        }
        #pragma unroll
        for (int o = 16; o > 0; o >>= 1)
            s += __shfl_xor_sync(0xffffffffu, s, o);
        if (lane == 0) {
            const float rv = fmaxf(s + bias[f], 0.0f);
            sval[j] = rv;
            acts[(size_t)b * DICT + f] = rv;
        }
    }
    __syncthreads();

    float acc0 = 0.0f, acc1 = 0.0f, acc2 = 0.0f;
    const int d0 = tid, d1 = tid + 256, d2 = tid + 512;
    #pragma unroll 4
    for (int j = 0; j < TOPK; ++j) {
        const float* wr = g_wdecT + (size_t)sidx[j] * D_MODEL;
        const float  v  = sval[j];
        acc0 += v * wr[d0];
        acc1 += v * wr[d1];
        acc2 += v * wr[d2];
    }
    float* orow = recon + (size_t)b * D_MODEL;
    orow[d0] = acc0;
    orow[d1] = acc1;
    orow[d2] = acc2;
}

// ---------------------------------------------------------------------------
// Launch: out = [recon (B*D_MODEL) | acts (B*DICT)] fp32
// ---------------------------------------------------------------------------
extern "C" void kernel_launch(void* const* d_in, const int* in_sizes, int n_in,
                              void* d_out, int out_size)
{
    const float* x     = (const float*)d_in[0];
    const float* W_enc = (const float*)d_in[1];
    const float* b_enc = (const float*)d_in[2];
    const float* W_dec = (const float*)d_in[3];
    (void)in_sizes; (void)n_in; (void)out_size;   // k hardcoded to 64

    float* recon = (float*)d_out;
    float* acts  = (float*)d_out + (size_t)B_ROWS * D_MODEL;

    cudaFuncSetAttribute(hgemm_kernel,
                         cudaFuncAttributeMaxDynamicSharedMemorySize,
                         GEMM_SMEM_BYTES);
    cudaFuncSetAttribute(topk_kernel,
                         cudaFuncAttributeMaxDynamicSharedMemorySize,
                         TK_SMEM_BYTES);

    __half* xh; cudaGetSymbolAddress((void**)&xh, g_xh);
    __half* wh; cudaGetSymbolAddress((void**)&wh, g_wh);

    cvt_kernel<<<256, 256>>>(x,     xh, B_ROWS * D_MODEL / 4);
    cvt_kernel<<<1024, 256>>>(W_enc, wh, DICT * D_MODEL / 4);
    transpose_kernel<<<dim3(DICT / 32, D_MODEL / 32), dim3(32, 8)>>>(W_dec);
    hgemm_kernel<<<dim3(DICT / 128, B_ROWS / 128), 256, GEMM_SMEM_BYTES>>>(b_enc);
    topk_kernel<<<B_ROWS, TK_THREADS, TK_SMEM_BYTES>>>(x, W_enc, b_enc, acts);
    sparse_out_kernel<<<B_ROWS, 256>>>(x, W_enc, b_enc, acts, recon);
}